// round 17
// baseline (speedup 1.0000x reference)
#include <cuda_runtime.h>
#include <cuda_fp16.h>
#include <math.h>

#define DET 512
#define NB  16
#define NT  180
#define NPH 90
#define CW  768   // padded column width: detector index range [-128, 640)

// packed quad-columns: [b][ph][i] = (h2(gF_t,gF_u), h2(dF_t,dF_u), h2(gR_t,gR_u), h2(dR_t,dR_u))
static __device__ uint4 g_pk[(size_t)NB * NPH * CW];

__device__ __forceinline__ unsigned int h2_to_u32(__half2 h) {
    return *reinterpret_cast<unsigned int*>(&h);
}
__device__ __forceinline__ __half2 u32_to_h2(unsigned int u) {
    return *reinterpret_cast<__half2*>(&u);
}

#define ADD_F32X2(out, a, b) \
    asm("add.rn.f32x2 %0, %1, %2;" : "=l"(out) : "l"(a), "l"(b))
#define PACK_F32X2(out, lo, hi) \
    asm("mov.b64 %0, {%1, %2};" : "=l"(out) : "r"(lo), "r"(hi))
#define UNPACK_F32X2(lo, hi, in) \
    asm("mov.b64 {%0, %1}, %2;" : "=r"(lo), "=r"(hi) : "l"(in))

// ---------------------------------------------------------------------------
// Kernel 1 (fused): register-tiled Ram-Lak filter for 4 mirror-phases
// (8 angles) per block, then pack fp16 quad-columns straight to g_pk.
// Grid y = 23 tiles of 4 phases (92 slots; the 2 past NPH are computed
// but NOT stored). Conv core identical to R15 (bitwise-identical xf).
// ---------------------------------------------------------------------------
__global__ __launch_bounds__(256) void filter_pack_kernel(const float* __restrict__ x)
{
    const int b  = blockIdx.x;
    const int p0 = blockIdx.y * 4;            // phases p0..p0+3 (may exceed 89)
    const int tid = threadIdx.x;              // 0..255

    __shared__ __align__(16) float xs[DET][8];    // [m][slot]; 0-3 = t, 4-7 = u
    __shared__ float gsym[DET];                   // G(k), k = 2j-511 (odd)

    for (int j = tid; j < DET; j += 256) {
        float k = (float)(2 * j - 511);
        gsym[j] = -2.0f / (9.869604401089358f * k * k);
    }

    // load xs[m][a] = x[b][m][angle(a)]; clamp dead phases to valid reads
    const float* xb = x + (size_t)b * DET * NT;
    for (int i = tid; i < DET * 8; i += 256) {
        int m = i >> 3;
        int a = i & 7;
        int ph = p0 + (a & 3);
        if (ph > NPH - 1 + 2) ph = NPH;           // defensive (never hit)
        int angle = (a < 4) ? ph : ((ph == 0) ? 90 : 180 - ph);
        if (angle > NT - 1) angle = NT - 1;       // dead-phase clamp (t=90,91)
        xs[m][a] = xb[m * NT + angle];
    }
    __syncthreads();

    // register-tiled convolution (identical to Round-15 filter core)
    const int ah  = (tid >> 7) * 4;           // angle slots ah..ah+3
    const int t7  = tid & 127;
    const int par = t7 >> 6;                  // 0/1
    const int grp = t7 & 63;                  // 0..63
    const int dbase = par + 2 * grp;          // d_r = dbase + 128r

    float acc[4][4];
    #pragma unroll
    for (int r = 0; r < 4; r++) {
        const float* xr = &xs[dbase + 128 * r][ah];
        #pragma unroll
        for (int a = 0; a < 4; a++) acc[r][a] = 0.5f * xr[a];
    }

    const int mp = 1 - par;
    const int gb0 = par + grp + 255;
    for (int j = 0; j < 256; j++) {
        const int m = mp + 2 * j;
        const int gb = gb0 - j;
        float g0 = gsym[gb];
        float g1 = gsym[gb + 64];
        float g2 = gsym[gb + 128];
        float g3 = gsym[gb + 192];
        float4 xv = *(const float4*)&xs[m][ah];
        acc[0][0] = fmaf(g0, xv.x, acc[0][0]);
        acc[0][1] = fmaf(g0, xv.y, acc[0][1]);
        acc[0][2] = fmaf(g0, xv.z, acc[0][2]);
        acc[0][3] = fmaf(g0, xv.w, acc[0][3]);
        acc[1][0] = fmaf(g1, xv.x, acc[1][0]);
        acc[1][1] = fmaf(g1, xv.y, acc[1][1]);
        acc[1][2] = fmaf(g1, xv.z, acc[1][2]);
        acc[1][3] = fmaf(g1, xv.w, acc[1][3]);
        acc[2][0] = fmaf(g2, xv.x, acc[2][0]);
        acc[2][1] = fmaf(g2, xv.y, acc[2][1]);
        acc[2][2] = fmaf(g2, xv.z, acc[2][2]);
        acc[2][3] = fmaf(g2, xv.w, acc[2][3]);
        acc[3][0] = fmaf(g3, xv.x, acc[3][0]);
        acc[3][1] = fmaf(g3, xv.y, acc[3][1]);
        acc[3][2] = fmaf(g3, xv.z, acc[3][2]);
        acc[3][3] = fmaf(g3, xv.w, acc[3][3]);
    }
    __syncthreads();   // all conv reads of xs done

    // filtered values back into xs (same [d][slot] layout)
    #pragma unroll
    for (int r = 0; r < 4; r++) {
        float* xr = &xs[dbase + 128 * r][ah];
        #pragma unroll
        for (int a = 0; a < 4; a++) xr[a] = acc[r][a];
    }
    __syncthreads();

    // pack quad-columns; store ONLY valid phases (ph < NPH)
    #pragma unroll
    for (int q = 0; q < 4; q++) {
        const int ph = p0 + q;
        if (ph >= NPH) break;
        uint4* dst = g_pk + ((size_t)b * NPH + ph) * CW;
        for (int i = tid; i < CW; i += 256) {
            int dF  = i - 128;
            int dFp = i - 127;
            int dR  = 639 - i;
            int dR2 = 638 - i;
            bool inF  = (unsigned)dF  < DET;
            bool inFp = (unsigned)dFp < DET;
            bool inR  = (unsigned)dR  < DET;
            bool inR2 = (unsigned)dR2 < DET;
            float gFt = inF  ? xs[dF][q]       : 0.0f;
            float gFu = inF  ? xs[dF][4 + q]   : 0.0f;
            float pFt = inFp ? xs[dFp][q]      : 0.0f;
            float pFu = inFp ? xs[dFp][4 + q]  : 0.0f;
            float gRt = inR  ? xs[dR][q]       : 0.0f;
            float gRu = inR  ? xs[dR][4 + q]   : 0.0f;
            float pRt = inR2 ? xs[dR2][q]      : 0.0f;
            float pRu = inR2 ? xs[dR2][4 + q]  : 0.0f;
            uint4 e;
            e.x = h2_to_u32(__floats2half2_rn(gFt,       gFu));
            e.y = h2_to_u32(__floats2half2_rn(pFt - gFt, pFu - gFu));
            e.z = h2_to_u32(__floats2half2_rn(gRt,       gRu));
            e.w = h2_to_u32(__floats2half2_rn(pRt - gRt, pRu - gRu));
            dst[i] = e;
        }
    }
}

// ---------------------------------------------------------------------------
// Kernel 2: backprojection; pair-sum in half2 (HADD2 after half-swap) and
// packed f32x2 accumulation. 8 taps per 2 LDS.128 lookups.
// ---------------------------------------------------------------------------
#define TAPIDX(iy, i0, w)                                    \
    {   float _tm = __fadd_rd((iy), MAGIC);                  \
        (i0) = __float_as_int(_tm) & 0x3FF;                  \
        (w)  = (iy) - (_tm - MAGIC); }

__global__ __launch_bounds__(512, 4) void backproj_kernel(float* __restrict__ out)
{
    const int b  = blockIdx.z;
    const int x0 = blockIdx.x * 32;
    const int y0 = blockIdx.y * 64;
    const int tid = threadIdx.x;             // 0..511
    const int tx = tid & 31;
    const int ty = tid >> 5;                 // 0..15 ; i = y0+ty+16k, k<4

    __shared__ __align__(16) uint4 col[2][CW];
    __shared__ float2 cs[NPH];

    if (tid < NPH) {
        float rad = (float)tid * 0.017453292519943295f;
        float sv, cv;
        sincosf(rad, &sv, &cv);
        cs[tid] = make_float2(cv, sv);
    }

    const uint4* pkb = g_pk + (size_t)b * NPH * CW;

    col[0][tid] = pkb[tid];
    if (tid < CW - 512) col[0][tid + 512] = pkb[tid + 512];
    __syncthreads();

    unsigned long long accAB[4], accCD[4];   // packed (f32,f32)
    #pragma unroll
    for (int k = 0; k < 4; k++) { accAB[k] = 0ULL; accCD[k] = 0ULL; }

    const float fx = (float)(x0 + tx) - 255.5f;
    const float fy = (float)(y0 + ty) - 255.5f;
    const float lim = 65408.0f;
    const float MAGIC = 8388608.0f;

    const float fxmin = 255.5f - (float)(x0 + 31);
    const float fymin = 255.5f - (float)(y0 + 63);
    const bool active = (fxmin * fxmin + fymin * fymin) <= lim;

    for (int ph = 0; ph < NPH; ph++) {
        const int cur = ph & 1;
        {
            int pn = (ph + 1 < NPH) ? ph + 1 : ph;
            const uint4* src = pkb + (size_t)pn * CW;
            uint4* dstc = col[cur ^ 1];
            dstc[tid] = src[tid];
            if (tid < CW - 512) dstc[tid + 512] = src[tid + 512];
        }

        if (active) {
            const uint4* cp = col[cur];
            if (ph == 0) {
                float w; int i0; uint4 q;
                float iyj = fx + 383.5f;
                TAPIDX(iyj, i0, w); q = cp[i0];
                __half2 w2 = __float2half2_rn(w);
                float tf0 = __low2float(__hfma2(w2, u32_to_h2(q.y), u32_to_h2(q.x)));
                float tr0 = __low2float(__hfma2(w2, u32_to_h2(q.w), u32_to_h2(q.z)));
                #pragma unroll
                for (int k = 0; k < 4; k++) {
                    float iyi = (fy + 16.0f * (float)k) + 383.5f;
                    TAPIDX(iyi, i0, w); q = cp[i0];
                    __half2 wk = __float2half2_rn(w);
                    float tf9 = __high2float(__hfma2(wk, u32_to_h2(q.y), u32_to_h2(q.x)));
                    float tr9 = __high2float(__hfma2(wk, u32_to_h2(q.w), u32_to_h2(q.z)));
                    unsigned long long p1, p2;
                    PACK_F32X2(p1, __float_as_uint(tf0 + tr9), __float_as_uint(tr0 + tr9));
                    ADD_F32X2(accAB[k], accAB[k], p1);
                    PACK_F32X2(p2, __float_as_uint(tr0 + tf9), __float_as_uint(tf0 + tf9));
                    ADD_F32X2(accCD[k], accCD[k], p2);
                }
            } else {
                const float2 cst = cs[ph];
                const float c = cst.x, s = cst.y;
                const float base1 = fmaf(c, fx, fmaf(-s, fy, 383.5f));
                const float base2 = fmaf(c, fx, fmaf( s, fy, 383.5f));
                const float s16 = 16.0f * s;
                #pragma unroll
                for (int k = 0; k < 4; k++) {
                    float w1, w2f; int i01, i02;
                    float iy1 = fmaf(-s16, (float)k, base1);
                    float iy2 = fmaf( s16, (float)k, base2);
                    TAPIDX(iy1, i01, w1); uint4 q1 = cp[i01];
                    TAPIDX(iy2, i02, w2f); uint4 q2 = cp[i02];
                    __half2 hw1 = __float2half2_rn(w1);
                    __half2 hw2 = __float2half2_rn(w2f);
                    __half2 vf1 = __hfma2(hw1, u32_to_h2(q1.y), u32_to_h2(q1.x)); // (A@t, B@u)
                    __half2 vr1 = __hfma2(hw1, u32_to_h2(q1.w), u32_to_h2(q1.z)); // (C@t, D@u)
                    __half2 vf2 = __hfma2(hw2, u32_to_h2(q2.y), u32_to_h2(q2.x)); // (D@t, C@u)
                    __half2 vr2 = __hfma2(hw2, u32_to_h2(q2.w), u32_to_h2(q2.z)); // (B@t, A@u)
                    __half2 sAB = __hadd2(vf1,
                        u32_to_h2(__byte_perm(h2_to_u32(vr2), 0, 0x1032)));       // (A, B)
                    __half2 sCD = __hadd2(vr1,
                        u32_to_h2(__byte_perm(h2_to_u32(vf2), 0, 0x1032)));       // (C, D)
                    float2 fab = __half22float2(sAB);
                    float2 fcd = __half22float2(sCD);
                    unsigned long long pab, pcd;
                    PACK_F32X2(pab, __float_as_uint(fab.x), __float_as_uint(fab.y));
                    ADD_F32X2(accAB[k], accAB[k], pab);
                    PACK_F32X2(pcd, __float_as_uint(fcd.x), __float_as_uint(fcd.y));
                    ADD_F32X2(accCD[k], accCD[k], pcd);
                }
            }
        }
        __syncthreads();
    }

    const float scale = 0.008726646259971648f;   // pi/360
    float* ob = out + (size_t)b * DET * DET;
    const int x1 = x0 + tx;
    const int x2 = 511 - x1;
    #pragma unroll
    for (int k = 0; k < 4; k++) {
        int   py  = y0 + ty + 16 * k;
        int   qy  = 511 - py;
        float fyk = fy + 16.0f * (float)k;
        float m   = ((fx * fx + fyk * fyk) <= lim) ? scale : 0.0f;
        unsigned int uA, uB, uC, uD;
        UNPACK_F32X2(uA, uB, accAB[k]);
        UNPACK_F32X2(uC, uD, accCD[k]);
        ob[(size_t)py * DET + x1] = __uint_as_float(uA) * m;
        ob[(size_t)py * DET + x2] = __uint_as_float(uB) * m;
        ob[(size_t)qy * DET + x2] = __uint_as_float(uC) * m;
        ob[(size_t)qy * DET + x1] = __uint_as_float(uD) * m;
    }
}

extern "C" void kernel_launch(void* const* d_in, const int* in_sizes, int n_in,
                              void* d_out, int out_size)
{
    const float* x = (const float*)d_in[0];
    float* out = (float*)d_out;

    dim3 gf(NB, 23);          // 16 batches x 23 tiles of 4 phases (90 total)
    filter_pack_kernel<<<gf, 256>>>(x);

    dim3 gb(8, 4, NB);        // quadrant: 8x4 tiles of 32x64, per batch
    backproj_kernel<<<gb, 512>>>(out);
}